// round 1
// baseline (speedup 1.0000x reference)
#include <cuda_runtime.h>

// TemporalAttentionModel: fused per-(b,n) kernel.
// H = [X,STE] (48x128) -> q,k,v = relu(H@W + b) -> per-head temporal attention
// over T=48 -> out = relu(O@W15+b15)@W16 + b16.
// One CTA per (batch, node): grid = 16*500 = 8000, 384 threads (8 heads x 48 queries).

namespace {
constexpr int B_ = 16;
constexpr int T_ = 48;
constexpr int N_ = 500;
constexpr int D_ = 64;    // K*d = 8*8
constexpr int THREADS = 384;
constexpr int QP = 65;    // q/k/v smem pitch (odd -> conflict-free strided access)
constexpr int SMEM_FLOATS = T_ * 128 + 3 * T_ * QP;   // H + q,k,v
constexpr int SMEM_BYTES = SMEM_FLOATS * 4;           // 62,016 B
}

__global__ __launch_bounds__(THREADS, 2)
void temporal_attn_kernel(
    const float* __restrict__ X,   const float* __restrict__ STE,
    const float* __restrict__ W12, const float* __restrict__ b12,
    const float* __restrict__ W13, const float* __restrict__ b13,
    const float* __restrict__ W14, const float* __restrict__ b14,
    const float* __restrict__ W15, const float* __restrict__ b15,
    const float* __restrict__ W16, const float* __restrict__ b16,
    float* __restrict__ out)
{
    extern __shared__ float smem[];
    float* Hs = smem;                 // [48][128]
    float* Qs = smem + T_ * 128;      // [48][QP]
    float* Ks = Qs + T_ * QP;         // [48][QP]
    float* Vs = Ks + T_ * QP;         // [48][QP]

    const int blk = blockIdx.x;
    const int b   = blk / N_;
    const int n   = blk - b * N_;
    const int tid = threadIdx.x;

    // Base offset of row (b, t=0, n, 0); row stride along t is N_*D_.
    const int rowbase = (b * T_ * N_ + n) * D_;

    // ---------------- Phase 0: load H = concat(X, STE) ----------------
    for (int i = tid; i < T_ * 16; i += THREADS) {
        const int t  = i >> 4;
        const int c4 = (i & 15) * 4;
        const int g  = rowbase + t * (N_ * D_) + c4;
        const float4 xv = *reinterpret_cast<const float4*>(X + g);
        const float4 sv = *reinterpret_cast<const float4*>(STE + g);
        *reinterpret_cast<float4*>(&Hs[t * 128 + c4])      = xv;
        *reinterpret_cast<float4*>(&Hs[t * 128 + 64 + c4]) = sv;
    }
    __syncthreads();

    // ---------------- Phase 1: q,k,v = relu(H @ W + b) ----------------
    {
        const int j  = tid & 63;     // output column
        const int rg = tid >> 6;     // 0..5 row group; rows t = rg + 6*r
        const float* Ws[3] = {W12, W13, W14};
        const float* bs[3] = {b12, b13, b14};
        float* Os[3]       = {Qs, Ks, Vs};
        #pragma unroll
        for (int m = 0; m < 3; m++) {
            const float* W = Ws[m];
            float acc[8];
            #pragma unroll
            for (int r = 0; r < 8; r++) acc[r] = 0.f;
            #pragma unroll 4
            for (int kk = 0; kk < 128; kk += 4) {
                const float w0 = __ldg(W + (kk + 0) * 64 + j);
                const float w1 = __ldg(W + (kk + 1) * 64 + j);
                const float w2 = __ldg(W + (kk + 2) * 64 + j);
                const float w3 = __ldg(W + (kk + 3) * 64 + j);
                #pragma unroll
                for (int r = 0; r < 8; r++) {
                    const float4 h =
                        *reinterpret_cast<const float4*>(&Hs[(rg + 6 * r) * 128 + kk]);
                    acc[r] = fmaf(h.x, w0, acc[r]);
                    acc[r] = fmaf(h.y, w1, acc[r]);
                    acc[r] = fmaf(h.z, w2, acc[r]);
                    acc[r] = fmaf(h.w, w3, acc[r]);
                }
            }
            const float bias = __ldg(bs[m] + j);
            float* dst = Os[m];
            #pragma unroll
            for (int r = 0; r < 8; r++)
                dst[(rg + 6 * r) * QP + j] = fmaxf(acc[r] + bias, 0.f);
        }
    }
    __syncthreads();

    // ---------------- Phase 2: temporal attention, 1 thread = (head, query) ----------------
    {
        const int h    = tid / T_;        // 0..7
        const int tq   = tid - h * T_;    // 0..47
        const int hoff = h * 8;

        float qv[8];
        #pragma unroll
        for (int e = 0; e < 8; e++) qv[e] = Qs[tq * QP + hoff + e];

        float sc[T_];
        #pragma unroll
        for (int p = 0; p < T_; p++) {
            float s = 0.f;
            #pragma unroll
            for (int e = 0; e < 8; e++)
                s = fmaf(qv[e], Ks[p * QP + hoff + e], s);
            sc[p] = s * 0.3535533905932738f;   // 1/sqrt(8)
        }

        float mx = sc[0];
        #pragma unroll
        for (int p = 1; p < T_; p++) mx = fmaxf(mx, sc[p]);
        float sum = 0.f;
        #pragma unroll
        for (int p = 0; p < T_; p++) {
            const float e2 = __expf(sc[p] - mx);
            sc[p] = e2;
            sum += e2;
        }
        const float inv = 1.f / sum;

        float o[8];
        #pragma unroll
        for (int e = 0; e < 8; e++) o[e] = 0.f;
        #pragma unroll
        for (int p = 0; p < T_; p++) {
            const float a = sc[p] * inv;
            #pragma unroll
            for (int e = 0; e < 8; e++)
                o[e] = fmaf(a, Vs[p * QP + hoff + e], o[e]);
        }

        __syncthreads();   // all reads of Qs (q vectors) are done block-wide
        #pragma unroll
        for (int e = 0; e < 8; e++) Qs[tq * QP + hoff + e] = o[e];   // O -> Qs
    }
    __syncthreads();

    // ---------------- Phase 3: P = relu(O @ W15 + b15) -> Ks ----------------
    {
        const int j  = tid & 63;
        const int rg = tid >> 6;
        float acc[8];
        #pragma unroll
        for (int r = 0; r < 8; r++) acc[r] = 0.f;
        #pragma unroll 4
        for (int kk = 0; kk < 64; kk++) {
            const float w = __ldg(W15 + kk * 64 + j);
            #pragma unroll
            for (int r = 0; r < 8; r++)
                acc[r] = fmaf(Qs[(rg + 6 * r) * QP + kk], w, acc[r]);
        }
        const float bias = __ldg(b15 + j);
        #pragma unroll
        for (int r = 0; r < 8; r++)
            Ks[(rg + 6 * r) * QP + j] = fmaxf(acc[r] + bias, 0.f);
    }
    __syncthreads();

    // ---------------- Phase 4: out = P @ W16 + b16 ----------------
    {
        const int j  = tid & 63;
        const int rg = tid >> 6;
        float acc[8];
        #pragma unroll
        for (int r = 0; r < 8; r++) acc[r] = 0.f;
        #pragma unroll 4
        for (int kk = 0; kk < 64; kk++) {
            const float w = __ldg(W16 + kk * 64 + j);
            #pragma unroll
            for (int r = 0; r < 8; r++)
                acc[r] = fmaf(Ks[(rg + 6 * r) * QP + kk], w, acc[r]);
        }
        const float bias = __ldg(b16 + j);
        #pragma unroll
        for (int r = 0; r < 8; r++) {
            const int t = rg + 6 * r;
            out[rowbase + t * (N_ * D_) + j] = acc[r] + bias;
        }
    }
}

extern "C" void kernel_launch(void* const* d_in, const int* in_sizes, int n_in,
                              void* d_out, int out_size)
{
    const float* X   = (const float*)d_in[0];
    const float* STE = (const float*)d_in[1];
    const float* W12 = (const float*)d_in[2];
    const float* b12 = (const float*)d_in[3];
    const float* W13 = (const float*)d_in[4];
    const float* b13 = (const float*)d_in[5];
    const float* W14 = (const float*)d_in[6];
    const float* b14 = (const float*)d_in[7];
    const float* W15 = (const float*)d_in[8];
    const float* b15 = (const float*)d_in[9];
    const float* W16 = (const float*)d_in[10];
    const float* b16 = (const float*)d_in[11];
    float* out = (float*)d_out;

    cudaFuncSetAttribute(temporal_attn_kernel,
                         cudaFuncAttributeMaxDynamicSharedMemorySize, SMEM_BYTES);

    temporal_attn_kernel<<<B_ * N_, THREADS, SMEM_BYTES>>>(
        X, STE, W12, b12, W13, b13, W14, b14, W15, b15, W16, b16, out);
}

// round 2
// speedup vs baseline: 1.4086x; 1.4086x over previous
#include <cuda_runtime.h>

// TemporalAttentionModel: fused per-(b,n) kernel, round 2.
// L1-wavefront-optimized: QKV matmuls fused (share H loads), float4 LDS everywhere.

namespace {
constexpr int B_ = 16;
constexpr int T_ = 48;
constexpr int N_ = 500;
constexpr int D_ = 64;    // K*d = 8*8
constexpr int THREADS = 384;
constexpr int QP = 72;    // q/k/v smem pitch: multiple of 8 -> float4-aligned heads
constexpr int SMEM_FLOATS = T_ * 128 + 3 * T_ * QP;   // H + q,k,v = 16512
constexpr int SMEM_BYTES = SMEM_FLOATS * 4;           // 66,048 B
}

__global__ __launch_bounds__(THREADS, 2)
void temporal_attn_kernel(
    const float* __restrict__ X,   const float* __restrict__ STE,
    const float* __restrict__ W12, const float* __restrict__ b12,
    const float* __restrict__ W13, const float* __restrict__ b13,
    const float* __restrict__ W14, const float* __restrict__ b14,
    const float* __restrict__ W15, const float* __restrict__ b15,
    const float* __restrict__ W16, const float* __restrict__ b16,
    float* __restrict__ out)
{
    extern __shared__ float smem[];
    float* Hs = smem;                 // [48][128]
    float* Qs = smem + T_ * 128;      // [48][QP]
    float* Ks = Qs + T_ * QP;         // [48][QP]
    float* Vs = Ks + T_ * QP;         // [48][QP]

    const int blk = blockIdx.x;
    const int b   = blk / N_;
    const int n   = blk - b * N_;
    const int tid = threadIdx.x;

    const int rowbase = (b * T_ * N_ + n) * D_;   // (b, t=0, n, 0); t-stride = N_*D_

    // ---------------- Phase 0: load H = concat(X, STE) ----------------
    for (int i = tid; i < T_ * 16; i += THREADS) {
        const int t  = i >> 4;
        const int c4 = (i & 15) * 4;
        const int g  = rowbase + t * (N_ * D_) + c4;
        const float4 xv = *reinterpret_cast<const float4*>(X + g);
        const float4 sv = *reinterpret_cast<const float4*>(STE + g);
        *reinterpret_cast<float4*>(&Hs[t * 128 + c4])      = xv;
        *reinterpret_cast<float4*>(&Hs[t * 128 + 64 + c4]) = sv;
    }
    __syncthreads();

    // ---------------- Phase 1: q,k,v = relu(H @ W + b), fused over 3 matmuls ----------------
    {
        const int j  = tid & 63;     // output column
        const int rg = tid >> 6;     // 0..5; rows t = rg + 6*r
        float aq[8], ak[8], av[8];
        #pragma unroll
        for (int r = 0; r < 8; r++) { aq[r] = 0.f; ak[r] = 0.f; av[r] = 0.f; }

        #pragma unroll 2
        for (int kk = 0; kk < 128; kk += 4) {
            float wq[4], wk[4], wv[4];
            #pragma unroll
            for (int u = 0; u < 4; u++) {
                wq[u] = __ldg(W12 + (kk + u) * 64 + j);
                wk[u] = __ldg(W13 + (kk + u) * 64 + j);
                wv[u] = __ldg(W14 + (kk + u) * 64 + j);
            }
            #pragma unroll
            for (int r = 0; r < 8; r++) {
                const float4 h =
                    *reinterpret_cast<const float4*>(&Hs[(rg + 6 * r) * 128 + kk]);
                aq[r] = fmaf(h.x, wq[0], aq[r]); aq[r] = fmaf(h.y, wq[1], aq[r]);
                aq[r] = fmaf(h.z, wq[2], aq[r]); aq[r] = fmaf(h.w, wq[3], aq[r]);
                ak[r] = fmaf(h.x, wk[0], ak[r]); ak[r] = fmaf(h.y, wk[1], ak[r]);
                ak[r] = fmaf(h.z, wk[2], ak[r]); ak[r] = fmaf(h.w, wk[3], ak[r]);
                av[r] = fmaf(h.x, wv[0], av[r]); av[r] = fmaf(h.y, wv[1], av[r]);
                av[r] = fmaf(h.z, wv[2], av[r]); av[r] = fmaf(h.w, wv[3], av[r]);
            }
        }
        const float bq = __ldg(b12 + j);
        const float bk = __ldg(b13 + j);
        const float bv = __ldg(b14 + j);
        #pragma unroll
        for (int r = 0; r < 8; r++) {
            const int t = rg + 6 * r;
            Qs[t * QP + j] = fmaxf(aq[r] + bq, 0.f);
            Ks[t * QP + j] = fmaxf(ak[r] + bk, 0.f);
            Vs[t * QP + j] = fmaxf(av[r] + bv, 0.f);
        }
    }
    __syncthreads();

    // ---------------- Phase 2: temporal attention, 1 thread = (head, query) ----------------
    {
        const int h    = tid / T_;        // 0..7
        const int tq   = tid - h * T_;    // 0..47
        const int hoff = h * 8;

        const float4 q0 = *reinterpret_cast<const float4*>(&Qs[tq * QP + hoff]);
        const float4 q1 = *reinterpret_cast<const float4*>(&Qs[tq * QP + hoff + 4]);

        float sc[T_];
        #pragma unroll
        for (int p = 0; p < T_; p++) {
            const float4 k0 = *reinterpret_cast<const float4*>(&Ks[p * QP + hoff]);
            const float4 k1 = *reinterpret_cast<const float4*>(&Ks[p * QP + hoff + 4]);
            float s;
            s = q0.x * k0.x;
            s = fmaf(q0.y, k0.y, s); s = fmaf(q0.z, k0.z, s); s = fmaf(q0.w, k0.w, s);
            s = fmaf(q1.x, k1.x, s); s = fmaf(q1.y, k1.y, s);
            s = fmaf(q1.z, k1.z, s); s = fmaf(q1.w, k1.w, s);
            sc[p] = s * 0.3535533905932738f;   // 1/sqrt(8)
        }

        float mx = sc[0];
        #pragma unroll
        for (int p = 1; p < T_; p++) mx = fmaxf(mx, sc[p]);
        float sum = 0.f;
        #pragma unroll
        for (int p = 0; p < T_; p++) {
            const float e2 = __expf(sc[p] - mx);
            sc[p] = e2;
            sum += e2;
        }
        const float inv = 1.f / sum;

        float4 o0 = make_float4(0.f, 0.f, 0.f, 0.f);
        float4 o1 = make_float4(0.f, 0.f, 0.f, 0.f);
        #pragma unroll
        for (int p = 0; p < T_; p++) {
            const float a = sc[p] * inv;
            const float4 v0 = *reinterpret_cast<const float4*>(&Vs[p * QP + hoff]);
            const float4 v1 = *reinterpret_cast<const float4*>(&Vs[p * QP + hoff + 4]);
            o0.x = fmaf(a, v0.x, o0.x); o0.y = fmaf(a, v0.y, o0.y);
            o0.z = fmaf(a, v0.z, o0.z); o0.w = fmaf(a, v0.w, o0.w);
            o1.x = fmaf(a, v1.x, o1.x); o1.y = fmaf(a, v1.y, o1.y);
            o1.z = fmaf(a, v1.z, o1.z); o1.w = fmaf(a, v1.w, o1.w);
        }

        __syncthreads();   // all reads of Qs done block-wide before overwrite
        *reinterpret_cast<float4*>(&Qs[tq * QP + hoff])     = o0;
        *reinterpret_cast<float4*>(&Qs[tq * QP + hoff + 4]) = o1;
    }
    __syncthreads();

    // ---------------- Phase 3: P = relu(O @ W15 + b15) -> Ks ----------------
    {
        const int j  = tid & 63;
        const int rg = tid >> 6;
        float acc[8];
        #pragma unroll
        for (int r = 0; r < 8; r++) acc[r] = 0.f;
        #pragma unroll 2
        for (int kk = 0; kk < 64; kk += 4) {
            float w[4];
            #pragma unroll
            for (int u = 0; u < 4; u++) w[u] = __ldg(W15 + (kk + u) * 64 + j);
            #pragma unroll
            for (int r = 0; r < 8; r++) {
                const float4 o4 =
                    *reinterpret_cast<const float4*>(&Qs[(rg + 6 * r) * QP + kk]);
                acc[r] = fmaf(o4.x, w[0], acc[r]); acc[r] = fmaf(o4.y, w[1], acc[r]);
                acc[r] = fmaf(o4.z, w[2], acc[r]); acc[r] = fmaf(o4.w, w[3], acc[r]);
            }
        }
        const float bias = __ldg(b15 + j);
        #pragma unroll
        for (int r = 0; r < 8; r++)
            Ks[(rg + 6 * r) * QP + j] = fmaxf(acc[r] + bias, 0.f);
    }
    __syncthreads();

    // ---------------- Phase 4: out = P @ W16 + b16 ----------------
    {
        const int j  = tid & 63;
        const int rg = tid >> 6;
        float acc[8];
        #pragma unroll
        for (int r = 0; r < 8; r++) acc[r] = 0.f;
        #pragma unroll 2
        for (int kk = 0; kk < 64; kk += 4) {
            float w[4];
            #pragma unroll
            for (int u = 0; u < 4; u++) w[u] = __ldg(W16 + (kk + u) * 64 + j);
            #pragma unroll
            for (int r = 0; r < 8; r++) {
                const float4 p4 =
                    *reinterpret_cast<const float4*>(&Ks[(rg + 6 * r) * QP + kk]);
                acc[r] = fmaf(p4.x, w[0], acc[r]); acc[r] = fmaf(p4.y, w[1], acc[r]);
                acc[r] = fmaf(p4.z, w[2], acc[r]); acc[r] = fmaf(p4.w, w[3], acc[r]);
            }
        }
        const float bias = __ldg(b16 + j);
        #pragma unroll
        for (int r = 0; r < 8; r++) {
            const int t = rg + 6 * r;
            out[rowbase + t * (N_ * D_) + j] = acc[r] + bias;
        }
    }
}

extern "C" void kernel_launch(void* const* d_in, const int* in_sizes, int n_in,
                              void* d_out, int out_size)
{
    const float* X   = (const float*)d_in[0];
    const float* STE = (const float*)d_in[1];
    const float* W12 = (const float*)d_in[2];
    const float* b12 = (const float*)d_in[3];
    const float* W13 = (const float*)d_in[4];
    const float* b13 = (const float*)d_in[5];
    const float* W14 = (const float*)d_in[6];
    const float* b14 = (const float*)d_in[7];
    const float* W15 = (const float*)d_in[8];
    const float* b15 = (const float*)d_in[9];
    const float* W16 = (const float*)d_in[10];
    const float* b16 = (const float*)d_in[11];
    float* out = (float*)d_out;

    cudaFuncSetAttribute(temporal_attn_kernel,
                         cudaFuncAttributeMaxDynamicSharedMemorySize, SMEM_BYTES);

    temporal_attn_kernel<<<B_ * N_, THREADS, SMEM_BYTES>>>(
        X, STE, W12, b12, W13, b13, W14, b14, W15, b15, W16, b16, out);
}